// round 14
// baseline (speedup 1.0000x reference)
#include <cuda_runtime.h>

#define NBINS 256
#define LUTK  1024
#define SEGK  2048
#define NREP  4
#define HIST_BLOCKS 1184
#define MAP_BLOCKS  1184
#define SEG_INVALID 1.0e30f

// ---------------- device globals (scratch; no allocation allowed) ----------
__device__ int      g_hist[6][NBINS];
__device__ float    g_dx[3][NBINS];     // cdf_src per channel
__device__ float    g_dy[3][NBINS];     // pxmap per channel
__device__ float4   g_seg[3][SEGK];     // pure-bucket segment endpoints (P0x,P0y,P1x,P1y)
__device__ unsigned g_lut[3][LUTK];     // fallback search windows (jlo | jhi<<16)

// ---------------------------------------------------------------------------
__global__ void zero_hist_kernel() {
    int i = blockIdx.x * blockDim.x + threadIdx.x;
    if (i < 6 * NBINS) ((int*)g_hist)[i] = 0;
}

// exact match of ((img + 1.0f)*128.0f).astype(int32): two RN ops, trunc, clip
__device__ __forceinline__ int bin_of(float v) {
    float f = __fmul_rn(__fadd_rn(v, 1.0f), 128.0f);
    int b = (int)f;
    return b < 0 ? 0 : (b > 255 ? 255 : b);
}

// ---------------------------------------------------------------------------
// Histogram: float4 loads (channels of 4i..4i+3 are i%3,+1,+2,+0), scalar
// shared atomics (R9-validated), NREP replicas. Bit-exact per R13.
__global__ void __launch_bounds__(256) hist_kernel(const float4* __restrict__ src4,
                                                   const float4* __restrict__ tgt4,
                                                   long nquads,
                                                   const float* __restrict__ src,
                                                   const float* __restrict__ tgt,
                                                   long nfloats) {
    __shared__ int sh[NREP][6][NBINS];
    int t = threadIdx.x;
    for (int i = t; i < NREP * 6 * NBINS; i += blockDim.x) ((int*)sh)[i] = 0;
    __syncthreads();

    int rep = (t >> 5) & (NREP - 1);
    long stride = (long)gridDim.x * blockDim.x;
    long g0 = (long)blockIdx.x * blockDim.x + t;

    for (long i = g0; i < nquads; i += stride) {
        float4 a = src4[i];
        float4 b = tgt4[i];
        int cb = (int)(i % 3);
        int c1 = cb + 1 == 3 ? 0 : cb + 1;
        int c2 = c1 + 1 == 3 ? 0 : c1 + 1;
        atomicAdd(&sh[rep][cb][bin_of(a.x)], 1);
        atomicAdd(&sh[rep][c1][bin_of(a.y)], 1);
        atomicAdd(&sh[rep][c2][bin_of(a.z)], 1);
        atomicAdd(&sh[rep][cb][bin_of(a.w)], 1);
        atomicAdd(&sh[rep][3 + cb][bin_of(b.x)], 1);
        atomicAdd(&sh[rep][3 + c1][bin_of(b.y)], 1);
        atomicAdd(&sh[rep][3 + c2][bin_of(b.z)], 1);
        atomicAdd(&sh[rep][3 + cb][bin_of(b.w)], 1);
    }
    for (long e = nquads * 4 + g0; e < nfloats; e += stride) {
        int c = (int)(e % 3);
        atomicAdd(&sh[rep][c][bin_of(src[e])], 1);
        atomicAdd(&sh[rep][3 + c][bin_of(tgt[e])], 1);
    }
    __syncthreads();

    for (int i = t; i < 6 * NBINS; i += blockDim.x) {
        int s = 0;
        #pragma unroll
        for (int r = 0; r < NREP; r++) s += ((int*)sh[r])[i];
        if (s) atomicAdd(&((int*)g_hist)[i], s);
    }
}

// ---------------------------------------------------------------------------
__device__ __forceinline__ int sst256(const float* a, float x) {
    int lo = 0, hi = NBINS;
    while (lo < hi) { int m = (lo + hi) >> 1; if (a[m] >= x) hi = m; else lo = m + 1; }
    return lo;
}

// Full literal interior index computation (incl. duplicate walk): returns
// (i0, ind1) used by the reference for interior x.
__device__ __forceinline__ int2 interior_inds(const float* dxa, float x) {
    int j  = sst256(dxa, x);             // in [1,255] for interior x
    float a0 = dxa[j - 1], a1 = dxa[j];
    float da = fabsf(__fsub_rn(x, a0));
    float db = fabsf(__fsub_rn(x, a1));
    int nl = (da <= db);
    float v = nl ? a0 : a1;
    int ind1 = nl ? (j - 1) : j;
    while (ind1 > 0 && dxa[ind1 - 1] == v) --ind1;   // first occurrence
    int ind0 = ind1 - 1;
    int i0 = (ind0 < 0) ? ind0 + 256 : ind0;
    return make_int2(i0, ind1);
}

__global__ void build_kernel(int npix) {
    __shared__ float cs[3][NBINS], ct[3][NBINS], px[3][NBINS];
    __shared__ int   cum[6][NBINS];
    int t = threadIdx.x;   // 256 threads

    if (t < 6) {
        int acc = 0;
        for (int k = 0; k < NBINS; k++) { acc += g_hist[t][k]; cum[t][k] = acc; }
    }
    __syncthreads();

    float denomN = (float)(npix - 1);
    #pragma unroll
    for (int c = 0; c < 3; c++) {
        float ds = (float)(cum[c][t]     - cum[c][0]);
        float dt = (float)(cum[3 + c][t] - cum[3 + c][0]);
        cs[c][t] = __fsub_rn(__fdiv_rn(__fmul_rn(ds, 2.0f), denomN), 1.0f);
        ct[c][t] = __fsub_rn(__fdiv_rn(__fmul_rn(dt, 2.0f), denomN), 1.0f);
    }
    __syncthreads();

    // pxmap = interpolate(dx=cdf_tgt (n=256), dy=grid (m=512), x=cdf_src)
    #pragma unroll
    for (int c = 0; c < 3; c++) {
        const float* dxa = ct[c];
        float x = cs[c][t];

        int j  = sst256(dxa, x);
        int c0 = j - 1; c0 = c0 < 0 ? 0 : (c0 > 255 ? 255 : c0);
        int c1 = j;     c1 = c1 < 0 ? 0 : (c1 > 255 ? 255 : c1);
        float da = fabsf(__fsub_rn(x, dxa[c0]));
        float db = fabsf(__fsub_rn(x, dxa[c1]));
        int nearr = (da <= db) ? c0 : c1;
        float v = dxa[nearr];
        int ind1 = nearr;
        while (ind1 > 0 && dxa[ind1 - 1] == v) --ind1;
        int ind0 = ind1 - 1;
        int i0x = (ind0 < 0) ? ind0 + 256 : ind0;        // n = 256
        int i0y = (ind0 < 0) ? ind0 + 512 : ind0;        // m = 512
        float den = __fsub_rn(dxa[ind1], dxa[i0x]);
        float tt  = (den == 0.0f) ? 0.0f : __fdiv_rn(__fsub_rn(x, dxa[i0x]), den);
        float gy0 = __fsub_rn(__fdiv_rn((float)i0y,  256.0f), 1.0f);
        float gy1 = __fsub_rn(__fdiv_rn((float)ind1, 256.0f), 1.0f);
        float mid = __fmaf_rn(__fsub_rn(gy1, gy0), tt, gy0);
        float r = (x <= dxa[0]) ? -1.0f
                : ((x >= dxa[NBINS - 1]) ? 0.99609375f : mid);

        px[c][t] = r;
    }
    __syncthreads();

    #pragma unroll
    for (int c = 0; c < 3; c++) {
        g_dx[c][t] = cs[c][t];
        g_dy[c][t] = px[c][t];
    }

    // Fallback search-window LUT (conservative, identical-result).
    for (int i = t; i < 3 * LUTK; i += blockDim.x) {
        int c = i / LUTK, b = i % LUTK;
        float lo = (float)b       * (2.0f / LUTK) - 1.0f;
        float hi = (float)(b + 1) * (2.0f / LUTK) - 1.0f;
        int jlo = sst256(cs[c], lo) - 1;
        int jhi = sst256(cs[c], hi) + 1;
        jlo = jlo < 1   ? 1   : jlo;
        jhi = jhi > 255 ? 255 : jhi;
        if (jhi < jlo) jhi = jlo;
        g_lut[c][b] = (unsigned)jlo | ((unsigned)jhi << 16);
    }

    // Segment LUT: bucket b covers x in [b*w-1, (b+1)*w-1); widen both ends
    // to absorb bucket-index rounding. Pure iff full literal path picks the
    // same (i0, ind1) at both widened endpoints AND the bucket is strictly
    // interior. Monotonicity of j(x) and the near-decision makes endpoint
    // agreement sufficient for the whole bucket.
    const float W = (2.0f / SEGK) / 16.0f;
    for (int i = t; i < 3 * SEGK; i += blockDim.x) {
        int c = i / SEGK, b = i % SEGK;
        float xlo = (float)b       * (2.0f / SEGK) - 1.0f - W;
        float xhi = (float)(b + 1) * (2.0f / SEGK) - 1.0f + W;
        float4 s = make_float4(SEG_INVALID, 0.0f, 0.0f, 0.0f);
        if (xlo > cs[c][0] && xhi < cs[c][NBINS - 1]) {
            int2 i_lo = interior_inds(cs[c], xlo);
            int2 i_hi = interior_inds(cs[c], xhi);
            if (i_lo.x == i_hi.x && i_lo.y == i_hi.y) {
                s = make_float4(cs[c][i_lo.x], px[c][i_lo.x],
                                cs[c][i_lo.y], px[c][i_lo.y]);
            }
        }
        g_seg[c][b] = s;
    }
}

// ---------------------------------------------------------------------------
// Fallback: literal transcription (incl. duplicate walk), window-accelerated.
__device__ __forceinline__ float mapv_gen(const float* __restrict__ dxa,
                                          const float* __restrict__ dya,
                                          const unsigned* __restrict__ lut,
                                          float x) {
    int b = (int)__fmul_rn(__fadd_rn(x, 1.0f), (float)(LUTK / 2));
    b = b < 0 ? 0 : (b > LUTK - 1 ? LUTK - 1 : b);
    unsigned w = lut[b];
    int lo = (int)(w & 0xffffu), hi = (int)(w >> 16);
    while (lo < hi) { int m = (lo + hi) >> 1; if (dxa[m] >= x) hi = m; else lo = m + 1; }
    int j  = lo;
    float a0 = dxa[j - 1], a1 = dxa[j];
    float da = fabsf(__fsub_rn(x, a0));
    float db = fabsf(__fsub_rn(x, a1));
    int nl = (da <= db);
    float v = nl ? a0 : a1;
    int ind1 = nl ? (j - 1) : j;
    while (ind1 > 0 && dxa[ind1 - 1] == v) --ind1;
    int ind0 = ind1 - 1;
    int i0 = (ind0 < 0) ? ind0 + 256 : ind0;
    float d0  = dxa[i0];
    float den = __fsub_rn(dxa[ind1], d0);
    float tt  = (den == 0.0f) ? 0.0f : __fdiv_rn(__fsub_rn(x, d0), den);
    float y0  = dya[i0], y1 = dya[ind1];
    return __fmaf_rn(__fsub_rn(y1, y0), tt, y0);
}

// One value: clips -> segment-LUT fast path (1 LDG) -> literal fallback.
__device__ __forceinline__ float mapv_one(int c,
                                          const float (*s_dx)[NBINS],
                                          const float (*s_dy)[NBINS],
                                          const unsigned (*s_lut)[LUTK],
                                          const float* dx0, const float* dxl,
                                          const float* dy0, const float* dyl,
                                          float x) {
    if (x <= dx0[c]) return dy0[c];
    if (x >= dxl[c]) return dyl[c];
    int b = (int)__fmul_rn(__fadd_rn(x, 1.0f), (float)(SEGK / 2));
    b = b < 0 ? 0 : (b > SEGK - 1 ? SEGK - 1 : b);
    float4 s = __ldg(&g_seg[c][b]);
    if (s.x < 1.0e29f) {
        float den = __fsub_rn(s.z, s.x);
        float tt  = (den == 0.0f) ? 0.0f : __fdiv_rn(__fsub_rn(x, s.x), den);
        return __fmaf_rn(__fsub_rn(s.w, s.y), tt, s.y);
    }
    return mapv_gen(s_dx[c], s_dy[c], s_lut[c], x);
}

__global__ void __launch_bounds__(256, 8) map_kernel(const float4* __restrict__ src4,
                                                     float4* __restrict__ out4,
                                                     long nquads,
                                                     const float* __restrict__ src,
                                                     float* __restrict__ out,
                                                     long nfloats) {
    __shared__ float    s_dx[3][NBINS];
    __shared__ float    s_dy[3][NBINS];
    __shared__ unsigned s_lut[3][LUTK];
    int t = threadIdx.x;
    for (int i = t; i < 3 * NBINS; i += blockDim.x) {
        ((float*)s_dx)[i] = ((const float*)g_dx)[i];
        ((float*)s_dy)[i] = ((const float*)g_dy)[i];
    }
    for (int i = t; i < 3 * LUTK; i += blockDim.x)
        ((unsigned*)s_lut)[i] = ((const unsigned*)g_lut)[i];
    __syncthreads();

    float dx0[3], dxl[3], dy0[3], dyl[3];
    #pragma unroll
    for (int c = 0; c < 3; c++) {
        dx0[c] = s_dx[c][0]; dxl[c] = s_dx[c][NBINS - 1];
        dy0[c] = s_dy[c][0]; dyl[c] = s_dy[c][NBINS - 1];
    }

    long stride = (long)gridDim.x * blockDim.x;
    long g0 = (long)blockIdx.x * blockDim.x + t;
    for (long i = g0; i < nquads; i += stride) {
        float4 v = src4[i];
        int cb = (int)(i % 3);
        int c1 = cb + 1 == 3 ? 0 : cb + 1;
        int c2 = c1 + 1 == 3 ? 0 : c1 + 1;
        float4 r;
        r.x = mapv_one(cb, s_dx, s_dy, s_lut, dx0, dxl, dy0, dyl, v.x);
        r.y = mapv_one(c1, s_dx, s_dy, s_lut, dx0, dxl, dy0, dyl, v.y);
        r.z = mapv_one(c2, s_dx, s_dy, s_lut, dx0, dxl, dy0, dyl, v.z);
        r.w = mapv_one(cb, s_dx, s_dy, s_lut, dx0, dxl, dy0, dyl, v.w);
        out4[i] = r;
    }
    for (long e = nquads * 4 + g0; e < nfloats; e += stride) {
        int c = (int)(e % 3);
        out[e] = mapv_one(c, s_dx, s_dy, s_lut, dx0, dxl, dy0, dyl, src[e]);
    }
}

// ---------------------------------------------------------------------------
extern "C" void kernel_launch(void* const* d_in, const int* in_sizes, int n_in,
                              void* d_out, int out_size) {
    const float* src = (const float*)d_in[0];
    const float* tgt = (const float*)d_in[1];
    float* out = (float*)d_out;
    long nfloats = (long)out_size;     // output has exactly src's shape
    long nquads  = nfloats / 4;        // nfloats % 12 == 0
    int  npix    = (int)(nfloats / 3);

    zero_hist_kernel<<<6, 256>>>();
    hist_kernel<<<HIST_BLOCKS, 256>>>((const float4*)src, (const float4*)tgt, nquads,
                                      src, tgt, nfloats);
    build_kernel<<<1, 256>>>(npix);
    map_kernel<<<MAP_BLOCKS, 256>>>((const float4*)src, (float4*)out, nquads,
                                    src, out, nfloats);
}

// round 15
// speedup vs baseline: 1.3621x; 1.3621x over previous
#include <cuda_runtime.h>

#define NBINS 256
#define LUTK  1024
#define NREP  4
#define HIST_BLOCKS 1184
#define MAP_BLOCKS  1184

// ---------------- device globals (scratch; no allocation allowed) ----------
__device__ int      g_hist[6][NBINS];   // rows 0..2 = src ch0..2, rows 3..5 = tgt ch0..2
__device__ float    g_dx[3][NBINS];     // cdf_src per channel
__device__ float    g_dy[3][NBINS];     // pxmap per channel
__device__ unsigned g_lut[3][LUTK];     // packed (jlo | jhi<<16) search windows
__device__ int      g_nodup;            // 1 if all channels strictly increasing

// ---------------------------------------------------------------------------
__global__ void zero_hist_kernel() {
    int i = blockIdx.x * blockDim.x + threadIdx.x;
    if (i < 6 * NBINS) ((int*)g_hist)[i] = 0;
}

// exact match of ((img + 1.0f)*128.0f).astype(int32): two RN ops, trunc, clip
__device__ __forceinline__ int bin_of(float v) {
    float f = __fmul_rn(__fadd_rn(v, 1.0f), 128.0f);
    int b = (int)f;                                    // trunc toward zero
    return b < 0 ? 0 : (b > 255 ? 255 : b);
}

// ---------------------------------------------------------------------------
// Histogram: float4 loads (channels of 4i..4i+3 are i%3,+1,+2,+0), scalar
// shared atomics (R9-validated), NREP replicas. Bit-exact per R13.
__global__ void __launch_bounds__(256) hist_kernel(const float4* __restrict__ src4,
                                                   const float4* __restrict__ tgt4,
                                                   long nquads,
                                                   const float* __restrict__ src,
                                                   const float* __restrict__ tgt,
                                                   long nfloats) {
    __shared__ int sh[NREP][6][NBINS];
    int t = threadIdx.x;
    for (int i = t; i < NREP * 6 * NBINS; i += blockDim.x) ((int*)sh)[i] = 0;
    __syncthreads();

    int rep = (t >> 5) & (NREP - 1);
    long stride = (long)gridDim.x * blockDim.x;
    long g0 = (long)blockIdx.x * blockDim.x + t;

    for (long i = g0; i < nquads; i += stride) {
        float4 a = src4[i];
        float4 b = tgt4[i];
        int cb = (int)(i % 3);
        int c1 = cb + 1 == 3 ? 0 : cb + 1;
        int c2 = c1 + 1 == 3 ? 0 : c1 + 1;
        atomicAdd(&sh[rep][cb][bin_of(a.x)], 1);
        atomicAdd(&sh[rep][c1][bin_of(a.y)], 1);
        atomicAdd(&sh[rep][c2][bin_of(a.z)], 1);
        atomicAdd(&sh[rep][cb][bin_of(a.w)], 1);
        atomicAdd(&sh[rep][3 + cb][bin_of(b.x)], 1);
        atomicAdd(&sh[rep][3 + c1][bin_of(b.y)], 1);
        atomicAdd(&sh[rep][3 + c2][bin_of(b.z)], 1);
        atomicAdd(&sh[rep][3 + cb][bin_of(b.w)], 1);
    }
    for (long e = nquads * 4 + g0; e < nfloats; e += stride) {
        int c = (int)(e % 3);
        atomicAdd(&sh[rep][c][bin_of(src[e])], 1);
        atomicAdd(&sh[rep][3 + c][bin_of(tgt[e])], 1);
    }
    __syncthreads();

    for (int i = t; i < 6 * NBINS; i += blockDim.x) {
        int s = 0;
        #pragma unroll
        for (int r = 0; r < NREP; r++) s += ((int*)sh[r])[i];
        if (s) atomicAdd(&((int*)g_hist)[i], s);
    }
}

// ---------------------------------------------------------------------------
__device__ __forceinline__ int sst256(const float* a, float x) {
    int lo = 0, hi = NBINS;
    while (lo < hi) { int m = (lo + hi) >> 1; if (a[m] >= x) hi = m; else lo = m + 1; }
    return lo;
}

__global__ void build_kernel(int npix) {
    __shared__ float cs[3][NBINS], ct[3][NBINS];
    __shared__ int   cum[6][NBINS];
    __shared__ int   nd;
    int t = threadIdx.x;   // 256 threads

    if (t == 0) nd = 1;
    if (t < 6) {
        int acc = 0;
        for (int k = 0; k < NBINS; k++) { acc += g_hist[t][k]; cum[t][k] = acc; }
    }
    __syncthreads();

    float denomN = (float)(npix - 1);
    #pragma unroll
    for (int c = 0; c < 3; c++) {
        float ds = (float)(cum[c][t]     - cum[c][0]);
        float dt = (float)(cum[3 + c][t] - cum[3 + c][0]);
        cs[c][t] = __fsub_rn(__fdiv_rn(__fmul_rn(ds, 2.0f), denomN), 1.0f);
        ct[c][t] = __fsub_rn(__fdiv_rn(__fmul_rn(dt, 2.0f), denomN), 1.0f);
    }
    __syncthreads();

    // pxmap = interpolate(dx=cdf_tgt (n=256), dy=grid (m=512), x=cdf_src)
    #pragma unroll
    for (int c = 0; c < 3; c++) {
        const float* dxa = ct[c];
        float x = cs[c][t];

        int j  = sst256(dxa, x);
        int c0 = j - 1; c0 = c0 < 0 ? 0 : (c0 > 255 ? 255 : c0);
        int c1 = j;     c1 = c1 < 0 ? 0 : (c1 > 255 ? 255 : c1);
        float da = fabsf(__fsub_rn(x, dxa[c0]));
        float db = fabsf(__fsub_rn(x, dxa[c1]));
        int nearr = (da <= db) ? c0 : c1;
        float v = dxa[nearr];
        int ind1 = nearr;
        while (ind1 > 0 && dxa[ind1 - 1] == v) --ind1;   // first occurrence
        int ind0 = ind1 - 1;
        int i0x = (ind0 < 0) ? ind0 + 256 : ind0;        // n = 256
        int i0y = (ind0 < 0) ? ind0 + 512 : ind0;        // m = 512
        float den = __fsub_rn(dxa[ind1], dxa[i0x]);
        float tt  = (den == 0.0f) ? 0.0f : __fdiv_rn(__fsub_rn(x, dxa[i0x]), den);
        float gy0 = __fsub_rn(__fdiv_rn((float)i0y,  256.0f), 1.0f);
        float gy1 = __fsub_rn(__fdiv_rn((float)ind1, 256.0f), 1.0f);
        float mid = __fmaf_rn(__fsub_rn(gy1, gy0), tt, gy0);
        float r = (x <= dxa[0]) ? -1.0f
                : ((x >= dxa[NBINS - 1]) ? 0.99609375f : mid);

        g_dx[c][t] = x;      // cdf_src
        g_dy[c][t] = r;      // pxmap
        // strictly-increasing check (enables the no-duplicate fast path)
        if (t < NBINS - 1 && !(cs[c][t] < cs[c][t + 1])) atomicAnd(&nd, 0);
    }
    __syncthreads();
    if (t == 0) g_nodup = nd;

    // Conservative search-window LUT over [-1,1): identical-result accelerator.
    for (int i = t; i < 3 * LUTK; i += blockDim.x) {
        int c = i / LUTK, b = i % LUTK;
        float lo = (float)b       * (2.0f / LUTK) - 1.0f;
        float hi = (float)(b + 1) * (2.0f / LUTK) - 1.0f;
        int jlo = sst256(cs[c], lo) - 1;
        int jhi = sst256(cs[c], hi) + 1;
        jlo = jlo < 1   ? 1   : jlo;
        jhi = jhi > 255 ? 255 : jhi;
        if (jhi < jlo) jhi = jlo;
        g_lut[c][b] = (unsigned)jlo | ((unsigned)jhi << 16);
    }
}

// ---------------------------------------------------------------------------
// Fast path: R11 mapv with the duplicate-walk removed (valid when cs is
// strictly increasing: the first-occurrence walk is the identity). When !nl,
// dx[ind1]=a1 and dx[i0]=a0 are register reuses — no extra LDS.
__device__ __forceinline__ float mapv_fast(const float* __restrict__ dxa,
                                           const float* __restrict__ dya,
                                           const unsigned* __restrict__ lut,
                                           float x, float dx0, float dxl,
                                           float dy0, float dyl) {
    if (x <= dx0) return dy0;
    if (x >= dxl) return dyl;
    int b = (int)__fmul_rn(__fadd_rn(x, 1.0f), (float)(LUTK / 2));
    b = b < 0 ? 0 : (b > LUTK - 1 ? LUTK - 1 : b);
    unsigned w = lut[b];
    int lo = (int)(w & 0xffffu), hi = (int)(w >> 16);
    while (lo < hi) { int m = (lo + hi) >> 1; if (dxa[m] >= x) hi = m; else lo = m + 1; }
    int j = lo;                           // searchsorted(dxa, x) in [1,255]
    float a0 = dxa[j - 1], a1 = dxa[j];
    float da = fabsf(__fsub_rn(x, a0));
    float db = fabsf(__fsub_rn(x, a1));
    float d1, d0, y0, y1;
    if (da <= db) {                       // ind1 = j-1, i0 = j-2 (wrap 255)
        int i0 = (j >= 2) ? (j - 2) : (NBINS - 1);
        d1 = a0;
        d0 = dxa[i0];
        y0 = dya[i0];
        y1 = dya[j - 1];
    } else {                              // ind1 = j, i0 = j-1
        d1 = a1;
        d0 = a0;                          // register reuse, no LDS
        y0 = dya[j - 1];
        y1 = dya[j];
    }
    float den = __fsub_rn(d1, d0);
    float tt  = (den == 0.0f) ? 0.0f : __fdiv_rn(__fsub_rn(x, d0), den);
    return __fmaf_rn(__fsub_rn(y1, y0), tt, y0);
}

__global__ void __launch_bounds__(256, 8) map_fast_kernel(const float4* __restrict__ src4,
                                                          float4* __restrict__ out4,
                                                          long nquads,
                                                          const float* __restrict__ src,
                                                          float* __restrict__ out,
                                                          long nfloats) {
    if (!g_nodup) return;   // kernel-uniform; general kernel handles this case
    __shared__ float    s_dx[3][NBINS];
    __shared__ float    s_dy[3][NBINS];
    __shared__ unsigned s_lut[3][LUTK];
    int t = threadIdx.x;
    for (int i = t; i < 3 * NBINS; i += blockDim.x) {
        ((float*)s_dx)[i] = ((const float*)g_dx)[i];
        ((float*)s_dy)[i] = ((const float*)g_dy)[i];
    }
    for (int i = t; i < 3 * LUTK; i += blockDim.x)
        ((unsigned*)s_lut)[i] = ((const unsigned*)g_lut)[i];
    __syncthreads();

    float dx0[3], dxl[3], dy0[3], dyl[3];
    #pragma unroll
    for (int c = 0; c < 3; c++) {
        dx0[c] = s_dx[c][0]; dxl[c] = s_dx[c][NBINS - 1];
        dy0[c] = s_dy[c][0]; dyl[c] = s_dy[c][NBINS - 1];
    }

    long stride = (long)gridDim.x * blockDim.x;
    long g0 = (long)blockIdx.x * blockDim.x + t;
    for (long i = g0; i < nquads; i += stride) {
        float4 v = src4[i];
        int cb = (int)(i % 3);
        int c1 = cb + 1 == 3 ? 0 : cb + 1;
        int c2 = c1 + 1 == 3 ? 0 : c1 + 1;
        float4 r;
        r.x = mapv_fast(s_dx[cb], s_dy[cb], s_lut[cb], v.x, dx0[cb], dxl[cb], dy0[cb], dyl[cb]);
        r.y = mapv_fast(s_dx[c1], s_dy[c1], s_lut[c1], v.y, dx0[c1], dxl[c1], dy0[c1], dyl[c1]);
        r.z = mapv_fast(s_dx[c2], s_dy[c2], s_lut[c2], v.z, dx0[c2], dxl[c2], dy0[c2], dyl[c2]);
        r.w = mapv_fast(s_dx[cb], s_dy[cb], s_lut[cb], v.w, dx0[cb], dxl[cb], dy0[cb], dyl[cb]);
        out4[i] = r;
    }
    for (long e = nquads * 4 + g0; e < nfloats; e += stride) {
        int c = (int)(e % 3);
        out[e] = mapv_fast(s_dx[c], s_dy[c], s_lut[c], src[e],
                           dx0[c], dxl[c], dy0[c], dyl[c]);
    }
}

// ---------------------------------------------------------------------------
// General fallback (literal transcription incl. duplicate walk) — R11 mapv.
__device__ __forceinline__ float mapv_gen(const float* __restrict__ dxa,
                                          const float* __restrict__ dya,
                                          const unsigned* __restrict__ lut,
                                          float x, float dx0, float dxl,
                                          float dy0, float dyl) {
    if (x <= dx0) return dy0;
    if (x >= dxl) return dyl;
    int b = (int)__fmul_rn(__fadd_rn(x, 1.0f), (float)(LUTK / 2));
    b = b < 0 ? 0 : (b > LUTK - 1 ? LUTK - 1 : b);
    unsigned w = lut[b];
    int lo = (int)(w & 0xffffu), hi = (int)(w >> 16);
    while (lo < hi) { int m = (lo + hi) >> 1; if (dxa[m] >= x) hi = m; else lo = m + 1; }
    int j  = lo;
    float a0 = dxa[j - 1], a1 = dxa[j];
    float da = fabsf(__fsub_rn(x, a0));
    float db = fabsf(__fsub_rn(x, a1));
    int nl = (da <= db);
    float v = nl ? a0 : a1;
    int ind1 = nl ? (j - 1) : j;
    while (ind1 > 0 && dxa[ind1 - 1] == v) --ind1;   // first occurrence
    int ind0 = ind1 - 1;
    int i0 = (ind0 < 0) ? ind0 + 256 : ind0;
    float d0  = dxa[i0];
    float den = __fsub_rn(dxa[ind1], d0);
    float tt  = (den == 0.0f) ? 0.0f : __fdiv_rn(__fsub_rn(x, d0), den);
    float y0  = dya[i0], y1 = dya[ind1];
    return __fmaf_rn(__fsub_rn(y1, y0), tt, y0);
}

__global__ void __launch_bounds__(256, 8) map_gen_kernel(const float4* __restrict__ src4,
                                                         float4* __restrict__ out4,
                                                         long nquads,
                                                         const float* __restrict__ src,
                                                         float* __restrict__ out,
                                                         long nfloats) {
    if (g_nodup) return;   // fast kernel handled it
    __shared__ float    s_dx[3][NBINS];
    __shared__ float    s_dy[3][NBINS];
    __shared__ unsigned s_lut[3][LUTK];
    int t = threadIdx.x;
    for (int i = t; i < 3 * NBINS; i += blockDim.x) {
        ((float*)s_dx)[i] = ((const float*)g_dx)[i];
        ((float*)s_dy)[i] = ((const float*)g_dy)[i];
    }
    for (int i = t; i < 3 * LUTK; i += blockDim.x)
        ((unsigned*)s_lut)[i] = ((const unsigned*)g_lut)[i];
    __syncthreads();

    float dx0[3], dxl[3], dy0[3], dyl[3];
    #pragma unroll
    for (int c = 0; c < 3; c++) {
        dx0[c] = s_dx[c][0]; dxl[c] = s_dx[c][NBINS - 1];
        dy0[c] = s_dy[c][0]; dyl[c] = s_dy[c][NBINS - 1];
    }

    long stride = (long)gridDim.x * blockDim.x;
    long g0 = (long)blockIdx.x * blockDim.x + t;
    for (long i = g0; i < nquads; i += stride) {
        float4 v = src4[i];
        int cb = (int)(i % 3);
        int c1 = cb + 1 == 3 ? 0 : cb + 1;
        int c2 = c1 + 1 == 3 ? 0 : c1 + 1;
        float4 r;
        r.x = mapv_gen(s_dx[cb], s_dy[cb], s_lut[cb], v.x, dx0[cb], dxl[cb], dy0[cb], dyl[cb]);
        r.y = mapv_gen(s_dx[c1], s_dy[c1], s_lut[c1], v.y, dx0[c1], dxl[c1], dy0[c1], dyl[c1]);
        r.z = mapv_gen(s_dx[c2], s_dy[c2], s_lut[c2], v.z, dx0[c2], dxl[c2], dy0[c2], dyl[c2]);
        r.w = mapv_gen(s_dx[cb], s_dy[cb], s_lut[cb], v.w, dx0[cb], dxl[cb], dy0[cb], dyl[cb]);
        out4[i] = r;
    }
    for (long e = nquads * 4 + g0; e < nfloats; e += stride) {
        int c = (int)(e % 3);
        out[e] = mapv_gen(s_dx[c], s_dy[c], s_lut[c], src[e],
                          dx0[c], dxl[c], dy0[c], dyl[c]);
    }
}

// ---------------------------------------------------------------------------
extern "C" void kernel_launch(void* const* d_in, const int* in_sizes, int n_in,
                              void* d_out, int out_size) {
    const float* src = (const float*)d_in[0];
    const float* tgt = (const float*)d_in[1];
    float* out = (float*)d_out;
    long nfloats = (long)out_size;     // output has exactly src's shape
    long nquads  = nfloats / 4;        // nfloats % 12 == 0
    int  npix    = (int)(nfloats / 3);

    zero_hist_kernel<<<6, 256>>>();
    hist_kernel<<<HIST_BLOCKS, 256>>>((const float4*)src, (const float4*)tgt, nquads,
                                      src, tgt, nfloats);
    build_kernel<<<1, 256>>>(npix);
    map_fast_kernel<<<MAP_BLOCKS, 256>>>((const float4*)src, (float4*)out, nquads,
                                         src, out, nfloats);
    map_gen_kernel<<<MAP_BLOCKS, 256>>>((const float4*)src, (float4*)out, nquads,
                                        src, out, nfloats);
}